// round 7
// baseline (speedup 1.0000x reference)
#include <cuda_runtime.h>
#include <cuda_fp16.h>
#include <cstdint>
#include <math.h>

#define NN 50000
#define EE 800000
#define E2 (EE + NN)
#define HID 128
#define HEADS 4
#define OUTC 64
#define DEPTH 4
#define FEPS 1e-6f
#define NEG_SLOPE 0.2f

// ---------------- device scratch ----------------
__device__ float  g_h[(size_t)NN * HID];
__device__ __half g_lnh[(size_t)NN * HID];
__device__ __half g_xh[(size_t)NN * HEADS * HID];
__device__ float  g_as[2][(size_t)NN * HEADS];   // ping-pong per layer
__device__ float  g_ad[2][(size_t)NN * HEADS];
__device__ float  g_wa_s[DEPTH * 512];
__device__ float  g_wa_d[DEPTH * 512];
__device__ int    g_cnt[NN];
__device__ int    g_rowptr[NN + 1];
__device__ int    g_wp[NN];
__device__ int    g_src[E2];
__device__ int    g_bsum[64];
__device__ int    g_boff[64];

// ---------------- CSR build ----------------
__global__ void k_zero_cnt() {
    int i = blockIdx.x * blockDim.x + threadIdx.x;
    if (i < NN) g_cnt[i] = 0;
}
__device__ __forceinline__ int edge_src(const int* ei, int e) { return (e < EE) ? ei[e] : (e - EE); }
__device__ __forceinline__ int edge_dst(const int* ei, int e) { return (e < EE) ? ei[EE + e] : (e - EE); }

__global__ void k_count(const int* __restrict__ ei) {
    int e = blockIdx.x * blockDim.x + threadIdx.x;
    if (e < E2) atomicAdd(&g_cnt[edge_dst(ei, e)], 1);
}
__global__ void k_scan1() {
    __shared__ int sh[1024];
    int tid = threadIdx.x;
    int i = blockIdx.x * 1024 + tid;
    int v = (i < NN) ? g_cnt[i] : 0;
    sh[tid] = v;
    __syncthreads();
    for (int off = 1; off < 1024; off <<= 1) {
        int t = (tid >= off) ? sh[tid - off] : 0;
        __syncthreads();
        sh[tid] += t;
        __syncthreads();
    }
    if (i < NN) g_rowptr[i] = sh[tid] - v;
    if (tid == 1023) g_bsum[blockIdx.x] = sh[1023];
}
__global__ void k_scan2(int nblk) {
    __shared__ int sh[64];
    int tid = threadIdx.x;
    sh[tid] = (tid < nblk) ? g_bsum[tid] : 0;
    __syncthreads();
    if (tid == 0) {
        int acc = 0;
        for (int b = 0; b < nblk; b++) { g_boff[b] = acc; acc += sh[b]; }
        g_rowptr[NN] = acc;
    }
}
__global__ void k_scan3() {
    int i = blockIdx.x * blockDim.x + threadIdx.x;
    if (i < NN) {
        int r = g_rowptr[i] + g_boff[i >> 10];
        g_rowptr[i] = r;
        g_wp[i] = r;
    }
}
__global__ void k_fill(const int* __restrict__ ei) {
    int e = blockIdx.x * blockDim.x + threadIdx.x;
    if (e < E2) {
        int d = edge_dst(ei, e);
        int s = edge_src(ei, e);
        int pos = atomicAdd(&g_wp[d], 1);
        g_src[pos] = s;
    }
}

// ---------------- wa precompute: wa[layer][h*128+cin] ----------------
__global__ void k_wa(const float* __restrict__ W_conv, const float* __restrict__ asrc,
                     const float* __restrict__ adst) {
    int i = blockIdx.x;
    int t = threadIdx.x;  // 512: h = t>>7, cin = t&127
    int h = t >> 7, cin = t & 127;
    const float* W  = W_conv + (size_t)i * 128 * 512 + (size_t)cin * 512 + h * 128;
    const float* av = asrc + i * 512 + h * 128;
    const float* dv = adst + i * 512 + h * 128;
    float ss = 0.f, sd = 0.f;
#pragma unroll 8
    for (int o = 0; o < 128; o++) {
        float w = W[o];
        ss += w * av[o];
        sd += w * dv[o];
    }
    g_wa_s[i * 512 + t] = ss;
    g_wa_d[i * 512 + t] = sd;
}

// ---------------- fused LN + attention scalars (device-resolved pointers) ----------------
__device__ __forceinline__ void ln_attn_store(
    int n, int t, float v, int layer, int wbuf,
    const float* __restrict__ gamma, const float* __restrict__ beta,
    float* s4, float* s32)
{
    const float* was = g_wa_s + layer * 512;
    const float* wad = g_wa_d + layer * 512;
    int w = t >> 5, lane = t & 31;
    float s = v;
#pragma unroll
    for (int o = 16; o; o >>= 1) s += __shfl_xor_sync(0xffffffffu, s, o);
    if (lane == 0) s4[w] = s;
    __syncthreads();
    float mu = (s4[0] + s4[1] + s4[2] + s4[3]) * (1.0f / 128.0f);
    __syncthreads();
    float d = v - mu;
    float q = d * d;
#pragma unroll
    for (int o = 16; o; o >>= 1) q += __shfl_xor_sync(0xffffffffu, q, o);
    if (lane == 0) s4[w] = q;
    __syncthreads();
    float inv = rsqrtf((s4[0] + s4[1] + s4[2] + s4[3]) * (1.0f / 128.0f) + FEPS);
    float lv = d * inv * gamma[t] + beta[t];
    g_lnh[(size_t)n * 128 + t] = __float2half_rn(lv);
    float p[8];
#pragma unroll
    for (int h = 0; h < 4; h++) {
        p[h]     = lv * was[h * 128 + t];
        p[h + 4] = lv * wad[h * 128 + t];
    }
#pragma unroll
    for (int j = 0; j < 8; j++)
#pragma unroll
        for (int o = 16; o; o >>= 1) p[j] += __shfl_xor_sync(0xffffffffu, p[j], o);
    if (lane == 0) {
#pragma unroll
        for (int j = 0; j < 8; j++) s32[w * 8 + j] = p[j];
    }
    __syncthreads();
    if (t < 4)
        g_as[wbuf][n * 4 + t] = s32[t] + s32[8 + t] + s32[16 + t] + s32[24 + t];
    else if (t < 8)
        g_ad[wbuf][n * 4 + (t - 4)] = s32[t] + s32[8 + t] + s32[16 + t] + s32[24 + t];
}

// ---------------- input projection + LN(0) ----------------
__global__ void k_in_proj(const float* __restrict__ x, const float* __restrict__ Win,
                          const float* __restrict__ bin,
                          const float* __restrict__ gamma, const float* __restrict__ beta) {
    __shared__ float s4[4];
    __shared__ float s32[32];
    int n = blockIdx.x;
    int t = threadIdx.x;  // 128
    float x0 = x[n * 3 + 0], x1 = x[n * 3 + 1], x2 = x[n * 3 + 2];
    float v = x0 * Win[t] + x1 * Win[128 + t] + x2 * Win[256 + t] + bin[t];
    g_h[(size_t)n * 128 + t] = v;
    ln_attn_store(n, t, v, /*layer=*/0, /*wbuf=*/0, gamma, beta, s4, s32);
}

// ---------------- tensor-core GEMM 128x128 tile ----------------
#define ASTR 72

__device__ __forceinline__ void ldsm_x4(unsigned* r, unsigned addr) {
    asm volatile("ldmatrix.sync.aligned.m8n8.x4.shared.b16 {%0,%1,%2,%3}, [%4];"
                 : "=r"(r[0]), "=r"(r[1]), "=r"(r[2]), "=r"(r[3]) : "r"(addr));
}
__device__ __forceinline__ void ldsm_x2(unsigned* r, unsigned addr) {
    asm volatile("ldmatrix.sync.aligned.m8n8.x2.shared.b16 {%0,%1}, [%2];"
                 : "=r"(r[0]), "=r"(r[1]) : "r"(addr));
}
__device__ __forceinline__ void mma16816(float* c, const unsigned* a, const unsigned* b) {
    asm volatile("mma.sync.aligned.m16n8k16.row.col.f32.f16.f16.f32 "
                 "{%0,%1,%2,%3}, {%4,%5,%6,%7}, {%8,%9}, {%0,%1,%2,%3};"
                 : "+f"(c[0]), "+f"(c[1]), "+f"(c[2]), "+f"(c[3])
                 : "r"(a[0]), "r"(a[1]), "r"(a[2]), "r"(a[3]), "r"(b[0]), "r"(b[1]));
}

__global__ __launch_bounds__(256, 2) void k_gemm(const float* __restrict__ W) {
    __shared__ __half SA[128 * ASTR];
    __shared__ __half SB[128 * ASTR];
    int tid = threadIdx.x;
    int row0 = blockIdx.y * 128;
    int col0 = blockIdx.x * 128;
    int wid = tid >> 5, lane = tid & 31;
    int wm = wid & 3, wn = wid >> 2;
    int g = lane >> 2, tq = lane & 3;

    float acc[2][8][4];
#pragma unroll
    for (int i = 0; i < 2; i++)
#pragma unroll
        for (int j = 0; j < 8; j++)
#pragma unroll
            for (int q = 0; q < 4; q++) acc[i][j][q] = 0.f;

    unsigned sa_base = (unsigned)__cvta_generic_to_shared(SA);
    unsigned sb_base = (unsigned)__cvta_generic_to_shared(SB);

    for (int k0 = 0; k0 < 128; k0 += 64) {
#pragma unroll
        for (int l = 0; l < 4; l++) {
            int idx = tid + l * 256;
            int r = idx >> 3, c8 = (idx & 7) * 8;
            uint4 v = make_uint4(0, 0, 0, 0);
            if (row0 + r < NN)
                v = *(const uint4*)(g_lnh + (size_t)(row0 + r) * 128 + k0 + c8);
            *(uint4*)(SA + r * ASTR + c8) = v;
        }
#pragma unroll
        for (int l = 0; l < 8; l++) {
            int idx = tid + l * 256;
            int kk = idx >> 5, c4 = (idx & 31) * 4;
            float4 v = *(const float4*)(W + (size_t)(k0 + kk) * 512 + col0 + c4);
            SB[(c4 + 0) * ASTR + kk] = __float2half_rn(v.x);
            SB[(c4 + 1) * ASTR + kk] = __float2half_rn(v.y);
            SB[(c4 + 2) * ASTR + kk] = __float2half_rn(v.z);
            SB[(c4 + 3) * ASTR + kk] = __float2half_rn(v.w);
        }
        __syncthreads();

#pragma unroll
        for (int ks = 0; ks < 64; ks += 16) {
            unsigned af[2][4], bf[8][2];
            int acol = ks + ((lane >= 16) ? 8 : 0);
#pragma unroll
            for (int mf = 0; mf < 2; mf++) {
                int arow = wm * 32 + mf * 16 + (lane & 15);
                ldsm_x4(af[mf], sa_base + (arow * ASTR + acol) * 2);
            }
            int brow_k = ks + ((lane & 8) ? 8 : 0);
#pragma unroll
            for (int nf = 0; nf < 8; nf++) {
                int bn = wn * 64 + nf * 8 + (lane & 7);
                ldsm_x2(bf[nf], sb_base + (bn * ASTR + brow_k) * 2);
            }
#pragma unroll
            for (int mf = 0; mf < 2; mf++)
#pragma unroll
                for (int nf = 0; nf < 8; nf++)
                    mma16816(acc[mf][nf], af[mf], bf[nf]);
        }
        __syncthreads();
    }

#pragma unroll
    for (int mf = 0; mf < 2; mf++) {
#pragma unroll
        for (int nf = 0; nf < 8; nf++) {
            int col = col0 + wn * 64 + nf * 8 + tq * 2;
            int r1 = row0 + wm * 32 + mf * 16 + g;
            int r2 = r1 + 8;
            if (r1 < NN)
                *(__half2*)(g_xh + (size_t)r1 * 512 + col) =
                    __floats2half2_rn(acc[mf][nf][0], acc[mf][nf][1]);
            if (r2 < NN)
                *(__half2*)(g_xh + (size_t)r2 * 512 + col) =
                    __floats2half2_rn(acc[mf][nf][2], acc[mf][nf][3]);
        }
    }
}

// ---------------- aggregation + fused next-layer LN ----------------
#define CHUNK 256
__device__ __forceinline__ float lrelu(float x) { return x > 0.f ? x : NEG_SLOPE * x; }

__global__ void k_agg(const float* __restrict__ bconv, int do_ln, int nl, int rb,
                      const float* __restrict__ gamma, const float* __restrict__ beta) {
    const float* as_rd = g_as[rb];
    const float* ad_rd = g_ad[rb];
    int n = blockIdx.x;
    int t = threadIdx.x;                  // 128
    int h = t >> 5, lane = t & 31;
    int ch0 = lane * 4;
    int beg = g_rowptr[n], end = g_rowptr[n + 1];

    __shared__ float s_wf[4][CHUNK];
    __shared__ int   s_src[CHUNK];
    __shared__ float s_part[4][HID];
    __shared__ float red[4][4];
    __shared__ float s_z[4];
    __shared__ float s4[4];
    __shared__ float s32[32];

    float4 adv = *(const float4*)(ad_rd + (size_t)n * 4);

    float z0 = 0.f, z1 = 0.f, z2 = 0.f, z3 = 0.f;
    float a0 = 0.f, a1 = 0.f, a2 = 0.f, a3 = 0.f;

    const __half* xbase = g_xh + h * 128 + ch0;

    for (int cb = beg; cb < end; cb += CHUNK) {
        int ce = min(end, cb + CHUNK);
        for (int k = cb + t; k < ce; k += 128) {
            int s = g_src[k];
            float4 a = *(const float4*)(as_rd + (size_t)s * 4);
            float w0 = __expf(lrelu(a.x + adv.x));
            float w1 = __expf(lrelu(a.y + adv.y));
            float w2 = __expf(lrelu(a.z + adv.z));
            float w3 = __expf(lrelu(a.w + adv.w));
            s_wf[0][k - cb] = w0;
            s_wf[1][k - cb] = w1;
            s_wf[2][k - cb] = w2;
            s_wf[3][k - cb] = w3;
            s_src[k - cb] = s;
            z0 += w0; z1 += w1; z2 += w2; z3 += w3;
        }
        __syncthreads();
        int cnt = ce - cb;
#pragma unroll 4
        for (int k = 0; k < cnt; k++) {
            float wv = s_wf[h][k];
            uint2 u = *(const uint2*)(xbase + (size_t)s_src[k] * 512);
            float2 f0 = __half22float2(*(__half2*)&u.x);
            float2 f1 = __half22float2(*(__half2*)&u.y);
            a0 += wv * f0.x; a1 += wv * f0.y;
            a2 += wv * f1.x; a3 += wv * f1.y;
        }
        __syncthreads();
    }

#pragma unroll
    for (int o = 16; o; o >>= 1) {
        z0 += __shfl_xor_sync(0xffffffffu, z0, o);
        z1 += __shfl_xor_sync(0xffffffffu, z1, o);
        z2 += __shfl_xor_sync(0xffffffffu, z2, o);
        z3 += __shfl_xor_sync(0xffffffffu, z3, o);
    }
    if (lane == 0) { red[h][0] = z0; red[h][1] = z1; red[h][2] = z2; red[h][3] = z3; }
    __syncthreads();
    if (t == 0) {
#pragma unroll
        for (int hh = 0; hh < 4; hh++)
            s_z[hh] = red[0][hh] + red[1][hh] + red[2][hh] + red[3][hh];
    }
    __syncthreads();
    float iz = 1.0f / s_z[h];
    *(float4*)(&s_part[h][ch0]) = make_float4(a0 * iz, a1 * iz, a2 * iz, a3 * iz);
    __syncthreads();
    float r = 0.25f * (s_part[0][t] + s_part[1][t] + s_part[2][t] + s_part[3][t]) + bconv[t];
    float newh = g_h[(size_t)n * HID + t] + fmaxf(r, 0.f);
    g_h[(size_t)n * HID + t] = newh;

    if (do_ln) {
        __syncthreads();
        ln_attn_store(n, t, newh, nl, rb ^ 1, gamma, beta, s4, s32);
    }
}

// ---------------- output projection ----------------
__global__ void k_out_proj(const float* __restrict__ W, const float* __restrict__ b,
                           float* __restrict__ out) {
    int n = blockIdx.x;
    __shared__ float sh[128];
    int t = threadIdx.x;  // 64
    sh[t] = g_h[(size_t)n * 128 + t];
    sh[t + 64] = g_h[(size_t)n * 128 + 64 + t];
    __syncthreads();
    float s = b[t];
#pragma unroll
    for (int k = 0; k < 128; k++) s += sh[k] * W[k * 64 + t];
    out[(size_t)n * 64 + t] = s;
}

// ---------------- launch ----------------
extern "C" void kernel_launch(void* const* d_in, const int* in_sizes, int n_in,
                              void* d_out, int out_size) {
    const float* x       = (const float*)d_in[0];
    const int*   ei      = (const int*)d_in[1];
    const float* W_in    = (const float*)d_in[2];
    const float* b_in    = (const float*)d_in[3];
    const float* W_conv  = (const float*)d_in[4];
    const float* att_src = (const float*)d_in[5];
    const float* att_dst = (const float*)d_in[6];
    const float* b_conv  = (const float*)d_in[7];
    const float* ln_g    = (const float*)d_in[8];
    const float* ln_b    = (const float*)d_in[9];
    const float* W_out   = (const float*)d_in[10];
    const float* b_out   = (const float*)d_in[11];
    float* out = (float*)d_out;

    int nblk = (NN + 1023) / 1024;
    k_zero_cnt<<<(NN + 255) / 256, 256>>>();
    k_count<<<(E2 + 255) / 256, 256>>>(ei);
    k_scan1<<<nblk, 1024>>>();
    k_scan2<<<1, 64>>>(nblk);
    k_scan3<<<nblk, 1024>>>();
    k_fill<<<(E2 + 255) / 256, 256>>>(ei);

    k_wa<<<DEPTH, 512>>>(W_conv, att_src, att_dst);

    k_in_proj<<<NN, 128>>>(x, W_in, b_in, ln_g, ln_b);

    dim3 gemmGrid(512 / 128, (NN + 127) / 128);
    for (int i = 0; i < DEPTH; i++) {
        k_gemm<<<gemmGrid, 256>>>(W_conv + (size_t)i * HID * HEADS * HID);
        int do_ln = (i < DEPTH - 1);
        int nl = (i + 1 < DEPTH) ? i + 1 : 0;
        k_agg<<<NN, 128>>>(b_conv + i * HID, do_ln, nl, i & 1,
                           ln_g + nl * HID, ln_b + nl * HID);
    }

    k_out_proj<<<NN, 64>>>(W_out, b_out, out);
}

// round 8
// speedup vs baseline: 1.1670x; 1.1670x over previous
#include <cuda_runtime.h>
#include <cuda_fp16.h>
#include <cstdint>
#include <math.h>

#define NN 50000
#define EE 800000
#define E2 (EE + NN)
#define HID 128
#define HEADS 4
#define OUTC 64
#define DEPTH 4
#define FEPS 1e-6f
#define NEG_SLOPE 0.2f

// ---------------- device scratch ----------------
__device__ float  g_h[(size_t)NN * HID];
__device__ __half g_lnh[(size_t)NN * HID];
__device__ __half g_xh[(size_t)NN * HEADS * HID];
__device__ float  g_as[2][(size_t)NN * HEADS];   // ping-pong per layer
__device__ float  g_ad[2][(size_t)NN * HEADS];
__device__ float  g_wa_s[DEPTH * 512];
__device__ float  g_wa_d[DEPTH * 512];
__device__ int    g_cnt[NN];
__device__ int    g_rowptr[NN + 1];
__device__ int    g_wp[NN];
__device__ int    g_src[E2];
__device__ int    g_bsum[64];
__device__ int    g_boff[64];

// ---------------- CSR build ----------------
__global__ void k_zero_cnt() {
    int i = blockIdx.x * blockDim.x + threadIdx.x;
    if (i < NN) g_cnt[i] = 0;
}
__device__ __forceinline__ int edge_src(const int* ei, int e) { return (e < EE) ? ei[e] : (e - EE); }
__device__ __forceinline__ int edge_dst(const int* ei, int e) { return (e < EE) ? ei[EE + e] : (e - EE); }

__global__ void k_count(const int* __restrict__ ei) {
    int e = blockIdx.x * blockDim.x + threadIdx.x;
    if (e < E2) atomicAdd(&g_cnt[edge_dst(ei, e)], 1);
}
__global__ void k_scan1() {
    __shared__ int sh[1024];
    int tid = threadIdx.x;
    int i = blockIdx.x * 1024 + tid;
    int v = (i < NN) ? g_cnt[i] : 0;
    sh[tid] = v;
    __syncthreads();
    for (int off = 1; off < 1024; off <<= 1) {
        int t = (tid >= off) ? sh[tid - off] : 0;
        __syncthreads();
        sh[tid] += t;
        __syncthreads();
    }
    if (i < NN) g_rowptr[i] = sh[tid] - v;
    if (tid == 1023) g_bsum[blockIdx.x] = sh[1023];
}
__global__ void k_scan2(int nblk) {
    __shared__ int sh[64];
    int tid = threadIdx.x;
    sh[tid] = (tid < nblk) ? g_bsum[tid] : 0;
    __syncthreads();
    if (tid == 0) {
        int acc = 0;
        for (int b = 0; b < nblk; b++) { g_boff[b] = acc; acc += sh[b]; }
        g_rowptr[NN] = acc;
    }
}
__global__ void k_scan3() {
    int i = blockIdx.x * blockDim.x + threadIdx.x;
    if (i < NN) {
        int r = g_rowptr[i] + g_boff[i >> 10];
        g_rowptr[i] = r;
        g_wp[i] = r;
    }
}
__global__ void k_fill(const int* __restrict__ ei) {
    int e = blockIdx.x * blockDim.x + threadIdx.x;
    if (e < E2) {
        int d = edge_dst(ei, e);
        int s = edge_src(ei, e);
        int pos = atomicAdd(&g_wp[d], 1);
        g_src[pos] = s;
    }
}

// ---------------- wa precompute: wa[layer][h*128+cin] ----------------
__global__ void k_wa(const float* __restrict__ W_conv, const float* __restrict__ asrc,
                     const float* __restrict__ adst) {
    int i = blockIdx.x;
    int t = threadIdx.x;  // 512: h = t>>7, cin = t&127
    int h = t >> 7, cin = t & 127;
    const float* W  = W_conv + (size_t)i * 128 * 512 + (size_t)cin * 512 + h * 128;
    const float* av = asrc + i * 512 + h * 128;
    const float* dv = adst + i * 512 + h * 128;
    float ss = 0.f, sd = 0.f;
#pragma unroll 8
    for (int o = 0; o < 128; o++) {
        float w = W[o];
        ss += w * av[o];
        sd += w * dv[o];
    }
    g_wa_s[i * 512 + t] = ss;
    g_wa_d[i * 512 + t] = sd;
}

// ---------------- fused LN + attention scalars ----------------
__device__ __forceinline__ void ln_attn_store(
    int n, int t, float v, int layer, int wbuf,
    const float* __restrict__ gamma, const float* __restrict__ beta,
    float* s4, float* s32)
{
    const float* was = g_wa_s + layer * 512;
    const float* wad = g_wa_d + layer * 512;
    int w = t >> 5, lane = t & 31;
    float s = v;
#pragma unroll
    for (int o = 16; o; o >>= 1) s += __shfl_xor_sync(0xffffffffu, s, o);
    if (lane == 0) s4[w] = s;
    __syncthreads();
    float mu = (s4[0] + s4[1] + s4[2] + s4[3]) * (1.0f / 128.0f);
    __syncthreads();
    float d = v - mu;
    float q = d * d;
#pragma unroll
    for (int o = 16; o; o >>= 1) q += __shfl_xor_sync(0xffffffffu, q, o);
    if (lane == 0) s4[w] = q;
    __syncthreads();
    float inv = rsqrtf((s4[0] + s4[1] + s4[2] + s4[3]) * (1.0f / 128.0f) + FEPS);
    float lv = d * inv * gamma[t] + beta[t];
    g_lnh[(size_t)n * 128 + t] = __float2half_rn(lv);
    float p[8];
#pragma unroll
    for (int h = 0; h < 4; h++) {
        p[h]     = lv * was[h * 128 + t];
        p[h + 4] = lv * wad[h * 128 + t];
    }
#pragma unroll
    for (int j = 0; j < 8; j++)
#pragma unroll
        for (int o = 16; o; o >>= 1) p[j] += __shfl_xor_sync(0xffffffffu, p[j], o);
    if (lane == 0) {
#pragma unroll
        for (int j = 0; j < 8; j++) s32[w * 8 + j] = p[j];
    }
    __syncthreads();
    if (t < 4)
        g_as[wbuf][n * 4 + t] = s32[t] + s32[8 + t] + s32[16 + t] + s32[24 + t];
    else if (t < 8)
        g_ad[wbuf][n * 4 + (t - 4)] = s32[t] + s32[8 + t] + s32[16 + t] + s32[24 + t];
}

// ---------------- input projection + LN(0) ----------------
__global__ void k_in_proj(const float* __restrict__ x, const float* __restrict__ Win,
                          const float* __restrict__ bin,
                          const float* __restrict__ gamma, const float* __restrict__ beta) {
    __shared__ float s4[4];
    __shared__ float s32[32];
    int n = blockIdx.x;
    int t = threadIdx.x;  // 128
    float x0 = x[n * 3 + 0], x1 = x[n * 3 + 1], x2 = x[n * 3 + 2];
    float v = x0 * Win[t] + x1 * Win[128 + t] + x2 * Win[256 + t] + bin[t];
    g_h[(size_t)n * 128 + t] = v;
    ln_attn_store(n, t, v, /*layer=*/0, /*wbuf=*/0, gamma, beta, s4, s32);
}

// ---------------- tensor-core GEMM: BN=64, conflict-free k-major B staging ----------------
#define ASTR 72
#define SBSTR 72

__device__ __forceinline__ void ldsm_x4(unsigned* r, unsigned addr) {
    asm volatile("ldmatrix.sync.aligned.m8n8.x4.shared.b16 {%0,%1,%2,%3}, [%4];"
                 : "=r"(r[0]), "=r"(r[1]), "=r"(r[2]), "=r"(r[3]) : "r"(addr));
}
__device__ __forceinline__ void ldsm_x4_trans(unsigned* r, unsigned addr) {
    asm volatile("ldmatrix.sync.aligned.m8n8.x4.trans.shared.b16 {%0,%1,%2,%3}, [%4];"
                 : "=r"(r[0]), "=r"(r[1]), "=r"(r[2]), "=r"(r[3]) : "r"(addr));
}
__device__ __forceinline__ void mma16816(float* c, const unsigned* a, const unsigned* b) {
    asm volatile("mma.sync.aligned.m16n8k16.row.col.f32.f16.f16.f32 "
                 "{%0,%1,%2,%3}, {%4,%5,%6,%7}, {%8,%9}, {%0,%1,%2,%3};"
                 : "+f"(c[0]), "+f"(c[1]), "+f"(c[2]), "+f"(c[3])
                 : "r"(a[0]), "r"(a[1]), "r"(a[2]), "r"(a[3]), "r"(b[0]), "r"(b[1]));
}

__global__ __launch_bounds__(256, 2) void k_gemm(const float* __restrict__ W) {
    __shared__ __half SA[128 * ASTR];   // A row-major [row][k]
    __shared__ __half SB[64 * SBSTR];   // B k-major [kk][n]  (64 k rows x 64 n)
    int tid = threadIdx.x;
    int row0 = blockIdx.y * 128;
    int col0 = blockIdx.x * 64;
    int wid = tid >> 5, lane = tid & 31;
    int wm = wid & 3, wn = wid >> 2;     // warp tile: rows wm*32, cols wn*32
    int g = lane >> 2, tq = lane & 3;

    float acc[2][4][4];
#pragma unroll
    for (int i = 0; i < 2; i++)
#pragma unroll
        for (int j = 0; j < 4; j++)
#pragma unroll
            for (int q = 0; q < 4; q++) acc[i][j][q] = 0.f;

    unsigned sa_base = (unsigned)__cvta_generic_to_shared(SA);
    unsigned sb_base = (unsigned)__cvta_generic_to_shared(SB);

    for (int k0 = 0; k0 < 128; k0 += 64) {
        // stage A (fp16 copy): 128 rows x 64 halves = 1024 uint4, conflict-light
#pragma unroll
        for (int l = 0; l < 4; l++) {
            int idx = tid + l * 256;
            int r = idx >> 3, c8 = (idx & 7) * 8;
            uint4 v = make_uint4(0, 0, 0, 0);
            if (row0 + r < NN)
                v = *(const uint4*)(g_lnh + (size_t)(row0 + r) * 128 + k0 + c8);
            *(uint4*)(SA + r * ASTR + c8) = v;
        }
        // stage B k-major: 64 k rows x 64 n. float4 read -> STS.64, coalesced, conflict-free
#pragma unroll
        for (int l = 0; l < 4; l++) {
            int idx = tid + l * 256;             // 1024 float4
            int kk = idx >> 4, c4 = (idx & 15) * 4;
            float4 v = *(const float4*)(W + (size_t)(k0 + kk) * 512 + col0 + c4);
            __half2 h01 = __floats2half2_rn(v.x, v.y);
            __half2 h23 = __floats2half2_rn(v.z, v.w);
            uint2 pk = make_uint2(*(unsigned*)&h01, *(unsigned*)&h23);
            *(uint2*)(SB + kk * SBSTR + c4) = pk;
        }
        __syncthreads();

#pragma unroll
        for (int ks = 0; ks < 64; ks += 16) {
            unsigned af[2][4], bf[2][4];
            int acol = ks + ((lane >= 16) ? 8 : 0);
#pragma unroll
            for (int mf = 0; mf < 2; mf++) {
                int arow = wm * 32 + mf * 16 + (lane & 15);
                ldsm_x4(af[mf], sa_base + (arow * ASTR + acol) * 2);
            }
            // B fragments via trans ldsm from k-major tile:
            // lanes 0-15 -> col bcol (n-blocks 0,1 as r0,r1 k0-7/k8-15), lanes 16-31 -> bcol+8
            int brow = ks + (lane & 15);
#pragma unroll
            for (int nb = 0; nb < 2; nb++) {
                int bcol = wn * 32 + nb * 16 + ((lane >= 16) ? 8 : 0);
                ldsm_x4_trans(bf[nb], sb_base + (brow * SBSTR + bcol) * 2);
            }
#pragma unroll
            for (int mf = 0; mf < 2; mf++) {
                mma16816(acc[mf][0], af[mf], &bf[0][0]);
                mma16816(acc[mf][1], af[mf], &bf[0][2]);
                mma16816(acc[mf][2], af[mf], &bf[1][0]);
                mma16816(acc[mf][3], af[mf], &bf[1][2]);
            }
        }
        __syncthreads();
    }

    // epilogue: store xh fp16
#pragma unroll
    for (int mf = 0; mf < 2; mf++) {
#pragma unroll
        for (int nf = 0; nf < 4; nf++) {
            int col = col0 + wn * 32 + nf * 8 + tq * 2;
            int r1 = row0 + wm * 32 + mf * 16 + g;
            int r2 = r1 + 8;
            if (r1 < NN)
                *(__half2*)(g_xh + (size_t)r1 * 512 + col) =
                    __floats2half2_rn(acc[mf][nf][0], acc[mf][nf][1]);
            if (r2 < NN)
                *(__half2*)(g_xh + (size_t)r2 * 512 + col) =
                    __floats2half2_rn(acc[mf][nf][2], acc[mf][nf][3]);
        }
    }
}

// ---------------- aggregation + fused next-layer LN ----------------
#define CHUNK 256
__device__ __forceinline__ float lrelu(float x) { return x > 0.f ? x : NEG_SLOPE * x; }

__global__ void k_agg(const float* __restrict__ bconv, int do_ln, int nl, int rb,
                      const float* __restrict__ gamma, const float* __restrict__ beta) {
    const float* as_rd = g_as[rb];
    const float* ad_rd = g_ad[rb];
    int n = blockIdx.x;
    int t = threadIdx.x;                  // 128
    int h = t >> 5, lane = t & 31;
    int ch0 = lane * 4;
    int beg = g_rowptr[n], end = g_rowptr[n + 1];

    __shared__ float s_wf[4][CHUNK];
    __shared__ int   s_src[CHUNK];
    __shared__ float s_part[4][HID];
    __shared__ float red[4][4];
    __shared__ float s_z[4];
    __shared__ float s4[4];
    __shared__ float s32[32];

    float4 adv = *(const float4*)(ad_rd + (size_t)n * 4);

    float z0 = 0.f, z1 = 0.f, z2 = 0.f, z3 = 0.f;
    float a0 = 0.f, a1 = 0.f, a2 = 0.f, a3 = 0.f;

    const __half* xbase = g_xh + h * 128 + ch0;

    for (int cb = beg; cb < end; cb += CHUNK) {
        int ce = min(end, cb + CHUNK);
        for (int k = cb + t; k < ce; k += 128) {
            int s = g_src[k];
            float4 a = *(const float4*)(as_rd + (size_t)s * 4);
            float w0 = __expf(lrelu(a.x + adv.x));
            float w1 = __expf(lrelu(a.y + adv.y));
            float w2 = __expf(lrelu(a.z + adv.z));
            float w3 = __expf(lrelu(a.w + adv.w));
            s_wf[0][k - cb] = w0;
            s_wf[1][k - cb] = w1;
            s_wf[2][k - cb] = w2;
            s_wf[3][k - cb] = w3;
            s_src[k - cb] = s;
            z0 += w0; z1 += w1; z2 += w2; z3 += w3;
        }
        __syncthreads();
        int cnt = ce - cb;
#pragma unroll 4
        for (int k = 0; k < cnt; k++) {
            float wv = s_wf[h][k];
            uint2 u = *(const uint2*)(xbase + (size_t)s_src[k] * 512);
            float2 f0 = __half22float2(*(__half2*)&u.x);
            float2 f1 = __half22float2(*(__half2*)&u.y);
            a0 += wv * f0.x; a1 += wv * f0.y;
            a2 += wv * f1.x; a3 += wv * f1.y;
        }
        __syncthreads();
    }

#pragma unroll
    for (int o = 16; o; o >>= 1) {
        z0 += __shfl_xor_sync(0xffffffffu, z0, o);
        z1 += __shfl_xor_sync(0xffffffffu, z1, o);
        z2 += __shfl_xor_sync(0xffffffffu, z2, o);
        z3 += __shfl_xor_sync(0xffffffffu, z3, o);
    }
    if (lane == 0) { red[h][0] = z0; red[h][1] = z1; red[h][2] = z2; red[h][3] = z3; }
    __syncthreads();
    if (t == 0) {
#pragma unroll
        for (int hh = 0; hh < 4; hh++)
            s_z[hh] = red[0][hh] + red[1][hh] + red[2][hh] + red[3][hh];
    }
    __syncthreads();
    float iz = 1.0f / s_z[h];
    *(float4*)(&s_part[h][ch0]) = make_float4(a0 * iz, a1 * iz, a2 * iz, a3 * iz);
    __syncthreads();
    float r = 0.25f * (s_part[0][t] + s_part[1][t] + s_part[2][t] + s_part[3][t]) + bconv[t];
    float newh = g_h[(size_t)n * HID + t] + fmaxf(r, 0.f);
    g_h[(size_t)n * HID + t] = newh;

    if (do_ln) {
        __syncthreads();
        ln_attn_store(n, t, newh, nl, rb ^ 1, gamma, beta, s4, s32);
    }
}

// ---------------- output projection ----------------
__global__ void k_out_proj(const float* __restrict__ W, const float* __restrict__ b,
                           float* __restrict__ out) {
    int n = blockIdx.x;
    __shared__ float sh[128];
    int t = threadIdx.x;  // 64
    sh[t] = g_h[(size_t)n * 128 + t];
    sh[t + 64] = g_h[(size_t)n * 128 + 64 + t];
    __syncthreads();
    float s = b[t];
#pragma unroll
    for (int k = 0; k < 128; k++) s += sh[k] * W[k * 64 + t];
    out[(size_t)n * 64 + t] = s;
}

// ---------------- launch ----------------
extern "C" void kernel_launch(void* const* d_in, const int* in_sizes, int n_in,
                              void* d_out, int out_size) {
    const float* x       = (const float*)d_in[0];
    const int*   ei      = (const int*)d_in[1];
    const float* W_in    = (const float*)d_in[2];
    const float* b_in    = (const float*)d_in[3];
    const float* W_conv  = (const float*)d_in[4];
    const float* att_src = (const float*)d_in[5];
    const float* att_dst = (const float*)d_in[6];
    const float* b_conv  = (const float*)d_in[7];
    const float* ln_g    = (const float*)d_in[8];
    const float* ln_b    = (const float*)d_in[9];
    const float* W_out   = (const float*)d_in[10];
    const float* b_out   = (const float*)d_in[11];
    float* out = (float*)d_out;

    int nblk = (NN + 1023) / 1024;
    k_zero_cnt<<<(NN + 255) / 256, 256>>>();
    k_count<<<(E2 + 255) / 256, 256>>>(ei);
    k_scan1<<<nblk, 1024>>>();
    k_scan2<<<1, 64>>>(nblk);
    k_scan3<<<nblk, 1024>>>();
    k_fill<<<(E2 + 255) / 256, 256>>>(ei);

    k_wa<<<DEPTH, 512>>>(W_conv, att_src, att_dst);

    k_in_proj<<<NN, 128>>>(x, W_in, b_in, ln_g, ln_b);

    dim3 gemmGrid(512 / 64, (NN + 127) / 128);
    for (int i = 0; i < DEPTH; i++) {
        k_gemm<<<gemmGrid, 256>>>(W_conv + (size_t)i * HID * HEADS * HID);
        int do_ln = (i < DEPTH - 1);
        int nl = (i + 1 < DEPTH) ? i + 1 : 0;
        k_agg<<<NN, 128>>>(b_conv + i * HID, do_ln, nl, i & 1,
                           ln_g + nl * HID, ln_b + nl * HID);
    }

    k_out_proj<<<NN, 64>>>(W_out, b_out, out);
}

// round 9
// speedup vs baseline: 1.2580x; 1.0780x over previous
#include <cuda_runtime.h>
#include <cuda_fp16.h>
#include <cstdint>
#include <math.h>

#define NN 50000
#define EE 800000
#define E2 (EE + NN)
#define HID 128
#define HEADS 4
#define OUTC 64
#define DEPTH 4
#define FEPS 1e-6f
#define NEG_SLOPE 0.2f

// ---------------- device scratch ----------------
__device__ float  g_h[(size_t)NN * HID];
__device__ __half g_lnh[(size_t)NN * HID];
__device__ __half g_xh[(size_t)NN * HEADS * HID];
__device__ float  g_as[(size_t)NN * HEADS];
__device__ float  g_ad[(size_t)NN * HEADS];
__device__ float  g_wa_s[DEPTH * 512];
__device__ float  g_wa_d[DEPTH * 512];
__device__ int    g_cnt[NN];
__device__ int    g_rowptr[NN + 1];
__device__ int    g_wp[NN];
__device__ int    g_src[E2];
__device__ int    g_bsum[64];
__device__ int    g_boff[64];

// ---------------- CSR build ----------------
__global__ void k_zero_cnt() {
    int i = blockIdx.x * blockDim.x + threadIdx.x;
    if (i < NN) g_cnt[i] = 0;
}
__device__ __forceinline__ int edge_src(const int* ei, int e) { return (e < EE) ? ei[e] : (e - EE); }
__device__ __forceinline__ int edge_dst(const int* ei, int e) { return (e < EE) ? ei[EE + e] : (e - EE); }

__global__ void k_count(const int* __restrict__ ei) {
    int e = blockIdx.x * blockDim.x + threadIdx.x;
    if (e < E2) atomicAdd(&g_cnt[edge_dst(ei, e)], 1);
}
__global__ void k_scan1() {
    __shared__ int sh[1024];
    int tid = threadIdx.x;
    int i = blockIdx.x * 1024 + tid;
    int v = (i < NN) ? g_cnt[i] : 0;
    sh[tid] = v;
    __syncthreads();
    for (int off = 1; off < 1024; off <<= 1) {
        int t = (tid >= off) ? sh[tid - off] : 0;
        __syncthreads();
        sh[tid] += t;
        __syncthreads();
    }
    if (i < NN) g_rowptr[i] = sh[tid] - v;
    if (tid == 1023) g_bsum[blockIdx.x] = sh[1023];
}
__global__ void k_scan2(int nblk) {
    __shared__ int sh[64];
    int tid = threadIdx.x;
    sh[tid] = (tid < nblk) ? g_bsum[tid] : 0;
    __syncthreads();
    if (tid == 0) {
        int acc = 0;
        for (int b = 0; b < nblk; b++) { g_boff[b] = acc; acc += sh[b]; }
        g_rowptr[NN] = acc;
    }
}
__global__ void k_scan3() {
    int i = blockIdx.x * blockDim.x + threadIdx.x;
    if (i < NN) {
        int r = g_rowptr[i] + g_boff[i >> 10];
        g_rowptr[i] = r;
        g_wp[i] = r;
    }
}
__global__ void k_fill(const int* __restrict__ ei) {
    int e = blockIdx.x * blockDim.x + threadIdx.x;
    if (e < E2) {
        int d = edge_dst(ei, e);
        int s = edge_src(ei, e);
        int pos = atomicAdd(&g_wp[d], 1);
        g_src[pos] = s;
    }
}

// ---------------- wa precompute: wa[layer][h*128+cin] ----------------
__global__ void k_wa(const float* __restrict__ W_conv, const float* __restrict__ asrc,
                     const float* __restrict__ adst) {
    int i = blockIdx.x;
    int t = threadIdx.x;  // 512: h = t>>7, cin = t&127
    int h = t >> 7, cin = t & 127;
    const float* W  = W_conv + (size_t)i * 128 * 512 + (size_t)cin * 512 + h * 128;
    const float* av = asrc + i * 512 + h * 128;
    const float* dv = adst + i * 512 + h * 128;
    float ss = 0.f, sd = 0.f;
#pragma unroll 8
    for (int o = 0; o < 128; o++) {
        float w = W[o];
        ss += w * av[o];
        sd += w * dv[o];
    }
    g_wa_s[i * 512 + t] = ss;
    g_wa_d[i * 512 + t] = sd;
}

// ---------------- input projection ----------------
__global__ void k_in_proj(const float* __restrict__ x, const float* __restrict__ Win,
                          const float* __restrict__ bin) {
    int i = blockIdx.x * blockDim.x + threadIdx.x;
    if (i >= NN * HID) return;
    int n = i >> 7, c = i & 127;
    float x0 = x[n * 3 + 0], x1 = x[n * 3 + 1], x2 = x[n * 3 + 2];
    g_h[i] = x0 * Win[c] + x1 * Win[HID + c] + x2 * Win[2 * HID + c] + bin[c];
}

// ---------------- LN + attention scalars, warp per node (no syncthreads) ----------------
__global__ void k_lnattn(int layer, const float* __restrict__ gamma,
                         const float* __restrict__ beta) {
    int row = blockIdx.x * 4 + (threadIdx.x >> 5);
    if (row >= NN) return;
    int lane = threadIdx.x & 31;
    const float* was = g_wa_s + layer * 512;
    const float* wad = g_wa_d + layer * 512;

    float4 v = *(const float4*)(g_h + (size_t)row * 128 + lane * 4);
    float s = v.x + v.y + v.z + v.w;
#pragma unroll
    for (int o = 16; o; o >>= 1) s += __shfl_xor_sync(0xffffffffu, s, o);
    float mu = s * (1.0f / 128.0f);
    float d0 = v.x - mu, d1 = v.y - mu, d2 = v.z - mu, d3 = v.w - mu;
    float q = d0 * d0 + d1 * d1 + d2 * d2 + d3 * d3;
#pragma unroll
    for (int o = 16; o; o >>= 1) q += __shfl_xor_sync(0xffffffffu, q, o);
    float inv = rsqrtf(q * (1.0f / 128.0f) + FEPS);
    float4 gm = *(const float4*)(gamma + lane * 4);
    float4 bt = *(const float4*)(beta + lane * 4);
    float l0 = d0 * inv * gm.x + bt.x;
    float l1 = d1 * inv * gm.y + bt.y;
    float l2 = d2 * inv * gm.z + bt.z;
    float l3 = d3 * inv * gm.w + bt.w;
    __half2* op = (__half2*)(g_lnh + (size_t)row * 128 + lane * 4);
    op[0] = __floats2half2_rn(l0, l1);
    op[1] = __floats2half2_rn(l2, l3);

    float p[8];
#pragma unroll
    for (int h = 0; h < 4; h++) {
        float4 ws = *(const float4*)(was + h * 128 + lane * 4);
        float4 wd = *(const float4*)(wad + h * 128 + lane * 4);
        p[h]     = l0 * ws.x + l1 * ws.y + l2 * ws.z + l3 * ws.w;
        p[h + 4] = l0 * wd.x + l1 * wd.y + l2 * wd.z + l3 * wd.w;
    }
#pragma unroll
    for (int j = 0; j < 8; j++)
#pragma unroll
        for (int o = 16; o; o >>= 1) p[j] += __shfl_xor_sync(0xffffffffu, p[j], o);
    if (lane == 0) {
#pragma unroll
        for (int h = 0; h < 4; h++) {
            g_as[row * 4 + h] = p[h];
            g_ad[row * 4 + h] = p[h + 4];
        }
    }
}

// ---------------- tensor-core GEMM: BN=64, conflict-free k-major B staging ----------------
#define ASTR 72
#define SBSTR 72

__device__ __forceinline__ void ldsm_x4(unsigned* r, unsigned addr) {
    asm volatile("ldmatrix.sync.aligned.m8n8.x4.shared.b16 {%0,%1,%2,%3}, [%4];"
                 : "=r"(r[0]), "=r"(r[1]), "=r"(r[2]), "=r"(r[3]) : "r"(addr));
}
__device__ __forceinline__ void ldsm_x4_trans(unsigned* r, unsigned addr) {
    asm volatile("ldmatrix.sync.aligned.m8n8.x4.trans.shared.b16 {%0,%1,%2,%3}, [%4];"
                 : "=r"(r[0]), "=r"(r[1]), "=r"(r[2]), "=r"(r[3]) : "r"(addr));
}
__device__ __forceinline__ void mma16816(float* c, const unsigned* a, const unsigned* b) {
    asm volatile("mma.sync.aligned.m16n8k16.row.col.f32.f16.f16.f32 "
                 "{%0,%1,%2,%3}, {%4,%5,%6,%7}, {%8,%9}, {%0,%1,%2,%3};"
                 : "+f"(c[0]), "+f"(c[1]), "+f"(c[2]), "+f"(c[3])
                 : "r"(a[0]), "r"(a[1]), "r"(a[2]), "r"(a[3]), "r"(b[0]), "r"(b[1]));
}

__global__ __launch_bounds__(256, 2) void k_gemm(const float* __restrict__ W) {
    __shared__ __half SA[128 * ASTR];
    __shared__ __half SB[64 * SBSTR];
    int tid = threadIdx.x;
    int row0 = blockIdx.y * 128;
    int col0 = blockIdx.x * 64;
    int wid = tid >> 5, lane = tid & 31;
    int wm = wid & 3, wn = wid >> 2;
    int g = lane >> 2, tq = lane & 3;

    float acc[2][4][4];
#pragma unroll
    for (int i = 0; i < 2; i++)
#pragma unroll
        for (int j = 0; j < 4; j++)
#pragma unroll
            for (int q = 0; q < 4; q++) acc[i][j][q] = 0.f;

    unsigned sa_base = (unsigned)__cvta_generic_to_shared(SA);
    unsigned sb_base = (unsigned)__cvta_generic_to_shared(SB);

    for (int k0 = 0; k0 < 128; k0 += 64) {
#pragma unroll
        for (int l = 0; l < 4; l++) {
            int idx = tid + l * 256;
            int r = idx >> 3, c8 = (idx & 7) * 8;
            uint4 v = make_uint4(0, 0, 0, 0);
            if (row0 + r < NN)
                v = *(const uint4*)(g_lnh + (size_t)(row0 + r) * 128 + k0 + c8);
            *(uint4*)(SA + r * ASTR + c8) = v;
        }
#pragma unroll
        for (int l = 0; l < 4; l++) {
            int idx = tid + l * 256;
            int kk = idx >> 4, c4 = (idx & 15) * 4;
            float4 v = *(const float4*)(W + (size_t)(k0 + kk) * 512 + col0 + c4);
            __half2 h01 = __floats2half2_rn(v.x, v.y);
            __half2 h23 = __floats2half2_rn(v.z, v.w);
            uint2 pk = make_uint2(*(unsigned*)&h01, *(unsigned*)&h23);
            *(uint2*)(SB + kk * SBSTR + c4) = pk;
        }
        __syncthreads();

#pragma unroll
        for (int ks = 0; ks < 64; ks += 16) {
            unsigned af[2][4], bf[2][4];
            int acol = ks + ((lane >= 16) ? 8 : 0);
#pragma unroll
            for (int mf = 0; mf < 2; mf++) {
                int arow = wm * 32 + mf * 16 + (lane & 15);
                ldsm_x4(af[mf], sa_base + (arow * ASTR + acol) * 2);
            }
            int brow = ks + (lane & 15);
#pragma unroll
            for (int nb = 0; nb < 2; nb++) {
                int bcol = wn * 32 + nb * 16 + ((lane >= 16) ? 8 : 0);
                ldsm_x4_trans(bf[nb], sb_base + (brow * SBSTR + bcol) * 2);
            }
#pragma unroll
            for (int mf = 0; mf < 2; mf++) {
                mma16816(acc[mf][0], af[mf], &bf[0][0]);
                mma16816(acc[mf][1], af[mf], &bf[0][2]);
                mma16816(acc[mf][2], af[mf], &bf[1][0]);
                mma16816(acc[mf][3], af[mf], &bf[1][2]);
            }
        }
        __syncthreads();
    }

#pragma unroll
    for (int mf = 0; mf < 2; mf++) {
#pragma unroll
        for (int nf = 0; nf < 4; nf++) {
            int col = col0 + wn * 32 + nf * 8 + tq * 2;
            int r1 = row0 + wm * 32 + mf * 16 + g;
            int r2 = r1 + 8;
            if (r1 < NN)
                *(__half2*)(g_xh + (size_t)r1 * 512 + col) =
                    __floats2half2_rn(acc[mf][nf][0], acc[mf][nf][1]);
            if (r2 < NN)
                *(__half2*)(g_xh + (size_t)r2 * 512 + col) =
                    __floats2half2_rn(acc[mf][nf][2], acc[mf][nf][3]);
        }
    }
}

// ---------------- aggregation: warp-per-head, all lanes per edge, no reductions ----------------
__device__ __forceinline__ float lrelu(float x) { return x > 0.f ? x : NEG_SLOPE * x; }

__global__ void k_agg(const float* __restrict__ bconv) {
    int n = blockIdx.x;
    int t = threadIdx.x;                  // 128
    int h = t >> 5, lane = t & 31;
    int beg = g_rowptr[n], end = g_rowptr[n + 1];

    __shared__ float s_part[4][HID];

    float adv = g_ad[n * 4 + h];
    const __half* xbase = g_xh + h * 128 + lane * 4;

    float z = 0.f, a0 = 0.f, a1 = 0.f, a2 = 0.f, a3 = 0.f;

#pragma unroll 4
    for (int k = beg; k < end; k++) {
        int s = g_src[k];
        float w = __expf(lrelu(g_as[s * 4 + h] + adv));
        uint2 u = *(const uint2*)(xbase + (size_t)s * 512);
        float2 f0 = __half22float2(*(__half2*)&u.x);
        float2 f1 = __half22float2(*(__half2*)&u.y);
        z += w;
        a0 += w * f0.x; a1 += w * f0.y;
        a2 += w * f1.x; a3 += w * f1.y;
    }

    float iz = 1.0f / z;
    *(float4*)(&s_part[h][lane * 4]) = make_float4(a0 * iz, a1 * iz, a2 * iz, a3 * iz);
    __syncthreads();
    float r = 0.25f * (s_part[0][t] + s_part[1][t] + s_part[2][t] + s_part[3][t]) + bconv[t];
    g_h[(size_t)n * HID + t] += fmaxf(r, 0.f);
}

// ---------------- output projection ----------------
__global__ void k_out_proj(const float* __restrict__ W, const float* __restrict__ b,
                           float* __restrict__ out) {
    int n = blockIdx.x;
    __shared__ float sh[128];
    int t = threadIdx.x;  // 64
    sh[t] = g_h[(size_t)n * 128 + t];
    sh[t + 64] = g_h[(size_t)n * 128 + 64 + t];
    __syncthreads();
    float s = b[t];
#pragma unroll
    for (int k = 0; k < 128; k++) s += sh[k] * W[k * 64 + t];
    out[(size_t)n * 64 + t] = s;
}

// ---------------- launch ----------------
extern "C" void kernel_launch(void* const* d_in, const int* in_sizes, int n_in,
                              void* d_out, int out_size) {
    const float* x       = (const float*)d_in[0];
    const int*   ei      = (const int*)d_in[1];
    const float* W_in    = (const float*)d_in[2];
    const float* b_in    = (const float*)d_in[3];
    const float* W_conv  = (const float*)d_in[4];
    const float* att_src = (const float*)d_in[5];
    const float* att_dst = (const float*)d_in[6];
    const float* b_conv  = (const float*)d_in[7];
    const float* ln_g    = (const float*)d_in[8];
    const float* ln_b    = (const float*)d_in[9];
    const float* W_out   = (const float*)d_in[10];
    const float* b_out   = (const float*)d_in[11];
    float* out = (float*)d_out;

    int nblk = (NN + 1023) / 1024;
    k_zero_cnt<<<(NN + 255) / 256, 256>>>();
    k_count<<<(E2 + 255) / 256, 256>>>(ei);
    k_scan1<<<nblk, 1024>>>();
    k_scan2<<<1, 64>>>(nblk);
    k_scan3<<<nblk, 1024>>>();
    k_fill<<<(E2 + 255) / 256, 256>>>(ei);

    k_wa<<<DEPTH, 512>>>(W_conv, att_src, att_dst);

    k_in_proj<<<(NN * HID + 255) / 256, 256>>>(x, W_in, b_in);

    dim3 gemmGrid(512 / 64, (NN + 127) / 128);
    for (int i = 0; i < DEPTH; i++) {
        k_lnattn<<<(NN + 3) / 4, 128>>>(i, ln_g + i * HID, ln_b + i * HID);
        k_gemm<<<gemmGrid, 256>>>(W_conv + (size_t)i * HID * HEADS * HID);
        k_agg<<<NN, 128>>>(b_conv + i * HID);
    }

    k_out_proj<<<NN, 64>>>(W_out, b_out, out);
}

// round 10
// speedup vs baseline: 1.4235x; 1.1316x over previous
#include <cuda_runtime.h>
#include <cuda_fp16.h>
#include <cstdint>
#include <math.h>

#define NN 50000
#define EE 800000
#define E2 (EE + NN)
#define HID 128
#define HEADS 4
#define OUTC 64
#define DEPTH 4
#define FEPS 1e-6f
#define NEG_SLOPE 0.2f

// ---------------- device scratch ----------------
__device__ float  g_h[(size_t)NN * HID];
__device__ __half g_lnh[(size_t)NN * HID];
__device__ __half g_xh[(size_t)NN * HEADS * HID];
__device__ __half g_wh[(size_t)DEPTH * HID * 512];   // fp16 W_conv
__device__ float  g_as[(size_t)NN * HEADS];
__device__ float  g_ad[(size_t)NN * HEADS];
__device__ float  g_wa_s[DEPTH * 512];
__device__ float  g_wa_d[DEPTH * 512];
__device__ int    g_cnt[NN];
__device__ int    g_rowptr[NN + 1];
__device__ int    g_wp[NN];
__device__ int    g_src[E2];
__device__ int    g_bsum[64];
__device__ int    g_boff[64];

// ---------------- CSR build ----------------
__global__ void k_zero_cnt() {
    int i = blockIdx.x * blockDim.x + threadIdx.x;
    if (i < NN) g_cnt[i] = 0;
}
__device__ __forceinline__ int edge_src(const int* ei, int e) { return (e < EE) ? ei[e] : (e - EE); }
__device__ __forceinline__ int edge_dst(const int* ei, int e) { return (e < EE) ? ei[EE + e] : (e - EE); }

__global__ void k_count(const int* __restrict__ ei) {
    int e = blockIdx.x * blockDim.x + threadIdx.x;
    if (e < E2) atomicAdd(&g_cnt[edge_dst(ei, e)], 1);
}
__global__ void k_scan1() {
    __shared__ int sh[1024];
    int tid = threadIdx.x;
    int i = blockIdx.x * 1024 + tid;
    int v = (i < NN) ? g_cnt[i] : 0;
    sh[tid] = v;
    __syncthreads();
    for (int off = 1; off < 1024; off <<= 1) {
        int t = (tid >= off) ? sh[tid - off] : 0;
        __syncthreads();
        sh[tid] += t;
        __syncthreads();
    }
    if (i < NN) g_rowptr[i] = sh[tid] - v;
    if (tid == 1023) g_bsum[blockIdx.x] = sh[1023];
}
__global__ void k_scan2(int nblk) {
    __shared__ int sh[64];
    int tid = threadIdx.x;
    sh[tid] = (tid < nblk) ? g_bsum[tid] : 0;
    __syncthreads();
    if (tid == 0) {
        int acc = 0;
        for (int b = 0; b < nblk; b++) { g_boff[b] = acc; acc += sh[b]; }
        g_rowptr[NN] = acc;
    }
}
__global__ void k_scan3() {
    int i = blockIdx.x * blockDim.x + threadIdx.x;
    if (i < NN) {
        int r = g_rowptr[i] + g_boff[i >> 10];
        g_rowptr[i] = r;
        g_wp[i] = r;
    }
}
__global__ void k_fill(const int* __restrict__ ei) {
    int e = blockIdx.x * blockDim.x + threadIdx.x;
    if (e < E2) {
        int d = edge_dst(ei, e);
        int s = edge_src(ei, e);
        int pos = atomicAdd(&g_wp[d], 1);
        g_src[pos] = s;
    }
}

// ---------------- W fp32 -> fp16 (all layers) ----------------
__global__ void k_wcvt(const float* __restrict__ W_conv) {
    int i = blockIdx.x * blockDim.x + threadIdx.x;   // over float4
    const int total = DEPTH * HID * 512 / 4;
    if (i >= total) return;
    float4 v = *(const float4*)(W_conv + (size_t)i * 4);
    __half2 h01 = __floats2half2_rn(v.x, v.y);
    __half2 h23 = __floats2half2_rn(v.z, v.w);
    *(uint2*)(g_wh + (size_t)i * 4) = make_uint2(*(unsigned*)&h01, *(unsigned*)&h23);
}

// ---------------- wa precompute: wa[layer][h*128+cin] ----------------
__global__ void k_wa(const float* __restrict__ W_conv, const float* __restrict__ asrc,
                     const float* __restrict__ adst) {
    int i = blockIdx.x;
    int t = threadIdx.x;  // 512: h = t>>7, cin = t&127
    int h = t >> 7, cin = t & 127;
    const float* W  = W_conv + (size_t)i * 128 * 512 + (size_t)cin * 512 + h * 128;
    const float* av = asrc + i * 512 + h * 128;
    const float* dv = adst + i * 512 + h * 128;
    float ss = 0.f, sd = 0.f;
#pragma unroll 8
    for (int o = 0; o < 128; o++) {
        float w = W[o];
        ss += w * av[o];
        sd += w * dv[o];
    }
    g_wa_s[i * 512 + t] = ss;
    g_wa_d[i * 512 + t] = sd;
}

// ---------------- input projection ----------------
__global__ void k_in_proj(const float* __restrict__ x, const float* __restrict__ Win,
                          const float* __restrict__ bin) {
    int i = blockIdx.x * blockDim.x + threadIdx.x;
    if (i >= NN * HID) return;
    int n = i >> 7, c = i & 127;
    float x0 = x[n * 3 + 0], x1 = x[n * 3 + 1], x2 = x[n * 3 + 2];
    g_h[i] = x0 * Win[c] + x1 * Win[HID + c] + x2 * Win[2 * HID + c] + bin[c];
}

// ---------------- LN + attention scalars, warp per node ----------------
__global__ void k_lnattn(int layer, const float* __restrict__ gamma,
                         const float* __restrict__ beta) {
    int row = blockIdx.x * 4 + (threadIdx.x >> 5);
    if (row >= NN) return;
    int lane = threadIdx.x & 31;
    const float* was = g_wa_s + layer * 512;
    const float* wad = g_wa_d + layer * 512;

    float4 v = *(const float4*)(g_h + (size_t)row * 128 + lane * 4);
    float s = v.x + v.y + v.z + v.w;
#pragma unroll
    for (int o = 16; o; o >>= 1) s += __shfl_xor_sync(0xffffffffu, s, o);
    float mu = s * (1.0f / 128.0f);
    float d0 = v.x - mu, d1 = v.y - mu, d2 = v.z - mu, d3 = v.w - mu;
    float q = d0 * d0 + d1 * d1 + d2 * d2 + d3 * d3;
#pragma unroll
    for (int o = 16; o; o >>= 1) q += __shfl_xor_sync(0xffffffffu, q, o);
    float inv = rsqrtf(q * (1.0f / 128.0f) + FEPS);
    float4 gm = *(const float4*)(gamma + lane * 4);
    float4 bt = *(const float4*)(beta + lane * 4);
    float l0 = d0 * inv * gm.x + bt.x;
    float l1 = d1 * inv * gm.y + bt.y;
    float l2 = d2 * inv * gm.z + bt.z;
    float l3 = d3 * inv * gm.w + bt.w;
    __half2* op = (__half2*)(g_lnh + (size_t)row * 128 + lane * 4);
    op[0] = __floats2half2_rn(l0, l1);
    op[1] = __floats2half2_rn(l2, l3);

    float p[8];
#pragma unroll
    for (int h = 0; h < 4; h++) {
        float4 ws = *(const float4*)(was + h * 128 + lane * 4);
        float4 wd = *(const float4*)(wad + h * 128 + lane * 4);
        p[h]     = l0 * ws.x + l1 * ws.y + l2 * ws.z + l3 * ws.w;
        p[h + 4] = l0 * wd.x + l1 * wd.y + l2 * wd.z + l3 * wd.w;
    }
#pragma unroll
    for (int j = 0; j < 8; j++)
#pragma unroll
        for (int o = 16; o; o >>= 1) p[j] += __shfl_xor_sync(0xffffffffu, p[j], o);
    if (lane == 0) {
#pragma unroll
        for (int h = 0; h < 4; h++) {
            g_as[row * 4 + h] = p[h];
            g_ad[row * 4 + h] = p[h + 4];
        }
    }
}

// ---------------- tensor-core GEMM: full-K staging, BN=64 ----------------
#define ASTR 136
#define SBSTR 72

__device__ __forceinline__ void ldsm_x4(unsigned* r, unsigned addr) {
    asm volatile("ldmatrix.sync.aligned.m8n8.x4.shared.b16 {%0,%1,%2,%3}, [%4];"
                 : "=r"(r[0]), "=r"(r[1]), "=r"(r[2]), "=r"(r[3]) : "r"(addr));
}
__device__ __forceinline__ void ldsm_x4_trans(unsigned* r, unsigned addr) {
    asm volatile("ldmatrix.sync.aligned.m8n8.x4.trans.shared.b16 {%0,%1,%2,%3}, [%4];"
                 : "=r"(r[0]), "=r"(r[1]), "=r"(r[2]), "=r"(r[3]) : "r"(addr));
}
__device__ __forceinline__ void mma16816(float* c, const unsigned* a, const unsigned* b) {
    asm volatile("mma.sync.aligned.m16n8k16.row.col.f32.f16.f16.f32 "
                 "{%0,%1,%2,%3}, {%4,%5,%6,%7}, {%8,%9}, {%0,%1,%2,%3};"
                 : "+f"(c[0]), "+f"(c[1]), "+f"(c[2]), "+f"(c[3])
                 : "r"(a[0]), "r"(a[1]), "r"(a[2]), "r"(a[3]), "r"(b[0]), "r"(b[1]));
}

__global__ __launch_bounds__(256, 2) void k_gemm(int layer) {
    __shared__ __half SA[128 * ASTR];   // A rows x full K=128
    __shared__ __half SB[128 * SBSTR];  // B k-major: 128 k rows x 64 n
    const __half* Wh = g_wh + (size_t)layer * HID * 512;
    int tid = threadIdx.x;
    int row0 = blockIdx.y * 128;
    int col0 = blockIdx.x * 64;
    int wid = tid >> 5, lane = tid & 31;
    int wm = wid & 3, wn = wid >> 2;
    int g = lane >> 2, tq = lane & 3;

    float acc[2][4][4];
#pragma unroll
    for (int i = 0; i < 2; i++)
#pragma unroll
        for (int j = 0; j < 4; j++)
#pragma unroll
            for (int q = 0; q < 4; q++) acc[i][j][q] = 0.f;

    unsigned sa_base = (unsigned)__cvta_generic_to_shared(SA);
    unsigned sb_base = (unsigned)__cvta_generic_to_shared(SB);

    // stage A: 128 rows x 128 halves = 2048 uint4, 8 per thread
#pragma unroll
    for (int l = 0; l < 8; l++) {
        int idx = tid + l * 256;
        int r = idx >> 4, c8 = (idx & 15) * 8;
        uint4 v = make_uint4(0, 0, 0, 0);
        if (row0 + r < NN)
            v = *(const uint4*)(g_lnh + (size_t)(row0 + r) * 128 + c8);
        *(uint4*)(SA + r * ASTR + c8) = v;
    }
    // stage B k-major from fp16 W: 128 k rows x 64 halves = 1024 uint4, 4 per thread
#pragma unroll
    for (int l = 0; l < 4; l++) {
        int idx = tid + l * 256;
        int kk = idx >> 3, c8 = (idx & 7) * 8;
        uint4 v = *(const uint4*)(Wh + (size_t)kk * 512 + col0 + c8);
        *(uint4*)(SB + kk * SBSTR + c8) = v;
    }
    __syncthreads();

#pragma unroll
    for (int ks = 0; ks < 128; ks += 16) {
        unsigned af[2][4], bf[2][4];
        int acol = ks + ((lane >= 16) ? 8 : 0);
#pragma unroll
        for (int mf = 0; mf < 2; mf++) {
            int arow = wm * 32 + mf * 16 + (lane & 15);
            ldsm_x4(af[mf], sa_base + (arow * ASTR + acol) * 2);
        }
        int brow = ks + (lane & 15);
#pragma unroll
        for (int nb = 0; nb < 2; nb++) {
            int bcol = wn * 32 + nb * 16 + ((lane >= 16) ? 8 : 0);
            ldsm_x4_trans(bf[nb], sb_base + (brow * SBSTR + bcol) * 2);
        }
#pragma unroll
        for (int mf = 0; mf < 2; mf++) {
            mma16816(acc[mf][0], af[mf], &bf[0][0]);
            mma16816(acc[mf][1], af[mf], &bf[0][2]);
            mma16816(acc[mf][2], af[mf], &bf[1][0]);
            mma16816(acc[mf][3], af[mf], &bf[1][2]);
        }
    }

    // epilogue: store xh fp16
#pragma unroll
    for (int mf = 0; mf < 2; mf++) {
#pragma unroll
        for (int nf = 0; nf < 4; nf++) {
            int col = col0 + wn * 32 + nf * 8 + tq * 2;
            int r1 = row0 + wm * 32 + mf * 16 + g;
            int r2 = r1 + 8;
            if (r1 < NN)
                *(__half2*)(g_xh + (size_t)r1 * 512 + col) =
                    __floats2half2_rn(acc[mf][nf][0], acc[mf][nf][1]);
            if (r2 < NN)
                *(__half2*)(g_xh + (size_t)r2 * 512 + col) =
                    __floats2half2_rn(acc[mf][nf][2], acc[mf][nf][3]);
        }
    }
}

// ---------------- aggregation: staged weights + all-lanes gather ----------------
#define CHUNK 128
__device__ __forceinline__ float lrelu(float x) { return x > 0.f ? x : NEG_SLOPE * x; }

__global__ void k_agg(const float* __restrict__ bconv) {
    int n = blockIdx.x;
    int t = threadIdx.x;                  // 128
    int h = t >> 5, lane = t & 31;
    int beg = g_rowptr[n], end = g_rowptr[n + 1];

    __shared__ int   s_src[CHUNK];
    __shared__ float s_w[CHUNK][4];
    __shared__ float s_part[4][HID];

    float4 adv = *(const float4*)(g_ad + (size_t)n * 4);
    const __half* xbase = g_xh + h * 128 + lane * 4;

    float z = 0.f, a0 = 0.f, a1 = 0.f, a2 = 0.f, a3 = 0.f;

    for (int cb = beg; cb < end; cb += CHUNK) {
        int ce = min(end, cb + CHUNK);
        int k = cb + t;
        if (k < ce) {
            int s = g_src[k];
            float4 a = *(const float4*)(g_as + (size_t)s * 4);
            s_src[t] = s;
            s_w[t][0] = __expf(lrelu(a.x + adv.x));
            s_w[t][1] = __expf(lrelu(a.y + adv.y));
            s_w[t][2] = __expf(lrelu(a.z + adv.z));
            s_w[t][3] = __expf(lrelu(a.w + adv.w));
        }
        __syncthreads();
        int cnt = ce - cb;
#pragma unroll 4
        for (int j = 0; j < cnt; j++) {
            float w = s_w[j][h];
            int s = s_src[j];
            uint2 u = *(const uint2*)(xbase + (size_t)s * 512);
            float2 f0 = __half22float2(*(__half2*)&u.x);
            float2 f1 = __half22float2(*(__half2*)&u.y);
            z += w;
            a0 += w * f0.x; a1 += w * f0.y;
            a2 += w * f1.x; a3 += w * f1.y;
        }
        __syncthreads();
    }

    float iz = 1.0f / z;
    *(float4*)(&s_part[h][lane * 4]) = make_float4(a0 * iz, a1 * iz, a2 * iz, a3 * iz);
    __syncthreads();
    float r = 0.25f * (s_part[0][t] + s_part[1][t] + s_part[2][t] + s_part[3][t]) + bconv[t];
    g_h[(size_t)n * HID + t] += fmaxf(r, 0.f);
}

// ---------------- output projection: 2 nodes per block ----------------
__global__ void k_out_proj(const float* __restrict__ W, const float* __restrict__ b,
                           float* __restrict__ out) {
    int half = threadIdx.x >> 6;          // 0 or 1
    int n = blockIdx.x * 2 + half;
    int t = threadIdx.x & 63;
    __shared__ float sh[2][128];
    if (n < NN) {
        sh[half][t] = g_h[(size_t)n * 128 + t];
        sh[half][t + 64] = g_h[(size_t)n * 128 + 64 + t];
    }
    __syncthreads();
    if (n >= NN) return;
    float s = b[t];
#pragma unroll
    for (int k = 0; k < 128; k++) s += sh[half][k] * W[k * 64 + t];
    out[(size_t)n * 64 + t] = s;
}

// ---------------- launch ----------------
extern "C" void kernel_launch(void* const* d_in, const int* in_sizes, int n_in,
                              void* d_out, int out_size) {
    const float* x       = (const float*)d_in[0];
    const int*   ei      = (const int*)d_in[1];
    const float* W_in    = (const float*)d_in[2];
    const float* b_in    = (const float*)d_in[3];
    const float* W_conv  = (const float*)d_in[4];
    const float* att_src = (const float*)d_in[5];
    const float* att_dst = (const float*)d_in[6];
    const float* b_conv  = (const float*)d_in[7];
    const float* ln_g    = (const float*)d_in[8];
    const float* ln_b    = (const float*)d_in[9];
    const float* W_out   = (const float*)d_in[10];
    const float* b_out   = (const float*)d_in[11];
    float* out = (float*)d_out;

    int nblk = (NN + 1023) / 1024;
    k_zero_cnt<<<(NN + 255) / 256, 256>>>();
    k_count<<<(E2 + 255) / 256, 256>>>(ei);
    k_scan1<<<nblk, 1024>>>();
    k_scan2<<<1, 64>>>(nblk);
    k_scan3<<<nblk, 1024>>>();
    k_fill<<<(E2 + 255) / 256, 256>>>(ei);

    k_wcvt<<<(DEPTH * HID * 512 / 4 + 255) / 256, 256>>>(W_conv);
    k_wa<<<DEPTH, 512>>>(W_conv, att_src, att_dst);

    k_in_proj<<<(NN * HID + 255) / 256, 256>>>(x, W_in, b_in);

    dim3 gemmGrid(512 / 64, (NN + 127) / 128);
    for (int i = 0; i < DEPTH; i++) {
        k_lnattn<<<(NN + 3) / 4, 128>>>(i, ln_g + i * HID, ln_b + i * HID);
        k_gemm<<<gemmGrid, 256>>>(i);
        k_agg<<<NN, 128>>>(b_conv + i * HID);
    }

    k_out_proj<<<(NN + 1) / 2, 128>>>(W_out, b_out, out);
}

// round 11
// speedup vs baseline: 1.4645x; 1.0288x over previous
#include <cuda_runtime.h>
#include <cuda_fp16.h>
#include <cstdint>
#include <math.h>

#define NN 50000
#define EE 800000
#define E2 (EE + NN)
#define HID 128
#define HEADS 4
#define OUTC 64
#define DEPTH 4
#define FEPS 1e-6f
#define NEG_SLOPE 0.2f

// ---------------- device scratch ----------------
__device__ float  g_h[(size_t)NN * HID];
__device__ __half g_lnh[(size_t)NN * HID];
__device__ __half g_xh[(size_t)NN * HEADS * HID];
__device__ __half g_wh[(size_t)DEPTH * HID * 512];   // fp16 W_conv
__device__ float  g_as[(size_t)NN * HEADS];
__device__ float  g_ad[(size_t)NN * HEADS];
__device__ float  g_wa_s[DEPTH * 512];
__device__ float  g_wa_d[DEPTH * 512];
__device__ int    g_cnt[NN];
__device__ int    g_rowptr[NN + 1];
__device__ int    g_wp[NN];
__device__ int    g_src[E2];
__device__ int    g_bsum[64];
__device__ int    g_boff[64];

// ---------------- CSR build ----------------
__global__ void k_zero_cnt() {
    int i = blockIdx.x * blockDim.x + threadIdx.x;
    if (i < NN) g_cnt[i] = 0;
}
__device__ __forceinline__ int edge_src(const int* ei, int e) { return (e < EE) ? ei[e] : (e - EE); }
__device__ __forceinline__ int edge_dst(const int* ei, int e) { return (e < EE) ? ei[EE + e] : (e - EE); }

__global__ void k_count(const int* __restrict__ ei) {
    int e = blockIdx.x * blockDim.x + threadIdx.x;
    if (e < E2) atomicAdd(&g_cnt[edge_dst(ei, e)], 1);
}
__global__ void k_scan1() {
    __shared__ int sh[1024];
    int tid = threadIdx.x;
    int i = blockIdx.x * 1024 + tid;
    int v = (i < NN) ? g_cnt[i] : 0;
    sh[tid] = v;
    __syncthreads();
    for (int off = 1; off < 1024; off <<= 1) {
        int t = (tid >= off) ? sh[tid - off] : 0;
        __syncthreads();
        sh[tid] += t;
        __syncthreads();
    }
    if (i < NN) g_rowptr[i] = sh[tid] - v;
    if (tid == 1023) g_bsum[blockIdx.x] = sh[1023];
}
__global__ void k_scan2(int nblk) {
    __shared__ int sh[64];
    int tid = threadIdx.x;
    sh[tid] = (tid < nblk) ? g_bsum[tid] : 0;
    __syncthreads();
    if (tid == 0) {
        int acc = 0;
        for (int b = 0; b < nblk; b++) { g_boff[b] = acc; acc += sh[b]; }
        g_rowptr[NN] = acc;
    }
}
__global__ void k_scan3() {
    int i = blockIdx.x * blockDim.x + threadIdx.x;
    if (i < NN) {
        int r = g_rowptr[i] + g_boff[i >> 10];
        g_rowptr[i] = r;
        g_wp[i] = r;
    }
}
__global__ void k_fill(const int* __restrict__ ei) {
    int e = blockIdx.x * blockDim.x + threadIdx.x;
    if (e < E2) {
        int d = edge_dst(ei, e);
        int s = edge_src(ei, e);
        int pos = atomicAdd(&g_wp[d], 1);
        g_src[pos] = s;
    }
}

// ---------------- W fp32 -> fp16 (all layers) ----------------
__global__ void k_wcvt(const float* __restrict__ W_conv) {
    int i = blockIdx.x * blockDim.x + threadIdx.x;   // over float4
    const int total = DEPTH * HID * 512 / 4;
    if (i >= total) return;
    float4 v = *(const float4*)(W_conv + (size_t)i * 4);
    __half2 h01 = __floats2half2_rn(v.x, v.y);
    __half2 h23 = __floats2half2_rn(v.z, v.w);
    *(uint2*)(g_wh + (size_t)i * 4) = make_uint2(*(unsigned*)&h01, *(unsigned*)&h23);
}

// ---------------- wa precompute: wa[layer][h*128+cin] ----------------
__global__ void k_wa(const float* __restrict__ W_conv, const float* __restrict__ asrc,
                     const float* __restrict__ adst) {
    int i = blockIdx.x;
    int t = threadIdx.x;  // 512: h = t>>7, cin = t&127
    int h = t >> 7, cin = t & 127;
    const float* W  = W_conv + (size_t)i * 128 * 512 + (size_t)cin * 512 + h * 128;
    const float* av = asrc + i * 512 + h * 128;
    const float* dv = adst + i * 512 + h * 128;
    float ss = 0.f, sd = 0.f;
#pragma unroll 8
    for (int o = 0; o < 128; o++) {
        float w = W[o];
        ss += w * av[o];
        sd += w * dv[o];
    }
    g_wa_s[i * 512 + t] = ss;
    g_wa_d[i * 512 + t] = sd;
}

// ---------------- input projection ----------------
__global__ void k_in_proj(const float* __restrict__ x, const float* __restrict__ Win,
                          const float* __restrict__ bin) {
    int i = blockIdx.x * blockDim.x + threadIdx.x;
    if (i >= NN * HID) return;
    int n = i >> 7, c = i & 127;
    float x0 = x[n * 3 + 0], x1 = x[n * 3 + 1], x2 = x[n * 3 + 2];
    g_h[i] = x0 * Win[c] + x1 * Win[HID + c] + x2 * Win[2 * HID + c] + bin[c];
}

// ---------------- LN + attention scalars, warp per node ----------------
__global__ void k_lnattn(int layer, const float* __restrict__ gamma,
                         const float* __restrict__ beta) {
    int row = blockIdx.x * 4 + (threadIdx.x >> 5);
    if (row >= NN) return;
    int lane = threadIdx.x & 31;
    const float* was = g_wa_s + layer * 512;
    const float* wad = g_wa_d + layer * 512;

    float4 v = *(const float4*)(g_h + (size_t)row * 128 + lane * 4);
    float s = v.x + v.y + v.z + v.w;
#pragma unroll
    for (int o = 16; o; o >>= 1) s += __shfl_xor_sync(0xffffffffu, s, o);
    float mu = s * (1.0f / 128.0f);
    float d0 = v.x - mu, d1 = v.y - mu, d2 = v.z - mu, d3 = v.w - mu;
    float q = d0 * d0 + d1 * d1 + d2 * d2 + d3 * d3;
#pragma unroll
    for (int o = 16; o; o >>= 1) q += __shfl_xor_sync(0xffffffffu, q, o);
    float inv = rsqrtf(q * (1.0f / 128.0f) + FEPS);
    float4 gm = *(const float4*)(gamma + lane * 4);
    float4 bt = *(const float4*)(beta + lane * 4);
    float l0 = d0 * inv * gm.x + bt.x;
    float l1 = d1 * inv * gm.y + bt.y;
    float l2 = d2 * inv * gm.z + bt.z;
    float l3 = d3 * inv * gm.w + bt.w;
    __half2* op = (__half2*)(g_lnh + (size_t)row * 128 + lane * 4);
    op[0] = __floats2half2_rn(l0, l1);
    op[1] = __floats2half2_rn(l2, l3);

    float p[8];
#pragma unroll
    for (int h = 0; h < 4; h++) {
        float4 ws = *(const float4*)(was + h * 128 + lane * 4);
        float4 wd = *(const float4*)(wad + h * 128 + lane * 4);
        p[h]     = l0 * ws.x + l1 * ws.y + l2 * ws.z + l3 * ws.w;
        p[h + 4] = l0 * wd.x + l1 * wd.y + l2 * wd.z + l3 * wd.w;
    }
#pragma unroll
    for (int j = 0; j < 8; j++)
#pragma unroll
        for (int o = 16; o; o >>= 1) p[j] += __shfl_xor_sync(0xffffffffu, p[j], o);
    if (lane == 0) {
#pragma unroll
        for (int h = 0; h < 4; h++) {
            g_as[row * 4 + h] = p[h];
            g_ad[row * 4 + h] = p[h + 4];
        }
    }
}

// ---------------- tensor-core GEMM: BN=128, full-K staging, k-major B ----------------
#define ASTR 136
#define SBSTR 136

__device__ __forceinline__ void ldsm_x4(unsigned* r, unsigned addr) {
    asm volatile("ldmatrix.sync.aligned.m8n8.x4.shared.b16 {%0,%1,%2,%3}, [%4];"
                 : "=r"(r[0]), "=r"(r[1]), "=r"(r[2]), "=r"(r[3]) : "r"(addr));
}
__device__ __forceinline__ void ldsm_x4_trans(unsigned* r, unsigned addr) {
    asm volatile("ldmatrix.sync.aligned.m8n8.x4.trans.shared.b16 {%0,%1,%2,%3}, [%4];"
                 : "=r"(r[0]), "=r"(r[1]), "=r"(r[2]), "=r"(r[3]) : "r"(addr));
}
__device__ __forceinline__ void mma16816(float* c, const unsigned* a, const unsigned* b) {
    asm volatile("mma.sync.aligned.m16n8k16.row.col.f32.f16.f16.f32 "
                 "{%0,%1,%2,%3}, {%4,%5,%6,%7}, {%8,%9}, {%0,%1,%2,%3};"
                 : "+f"(c[0]), "+f"(c[1]), "+f"(c[2]), "+f"(c[3])
                 : "r"(a[0]), "r"(a[1]), "r"(a[2]), "r"(a[3]), "r"(b[0]), "r"(b[1]));
}

__global__ __launch_bounds__(256, 2) void k_gemm(int layer) {
    __shared__ __half SA[128 * ASTR];   // A rows x full K=128
    __shared__ __half SB[128 * SBSTR];  // B k-major: 128 k rows x 128 n
    const __half* Wh = g_wh + (size_t)layer * HID * 512;
    int tid = threadIdx.x;
    int row0 = blockIdx.y * 128;
    int col0 = blockIdx.x * 128;
    int wid = tid >> 5, lane = tid & 31;
    int wm = wid & 3, wn = wid >> 2;     // warp tile: rows wm*32, cols wn*64
    int g = lane >> 2, tq = lane & 3;

    float acc[2][8][4];
#pragma unroll
    for (int i = 0; i < 2; i++)
#pragma unroll
        for (int j = 0; j < 8; j++)
#pragma unroll
            for (int q = 0; q < 4; q++) acc[i][j][q] = 0.f;

    unsigned sa_base = (unsigned)__cvta_generic_to_shared(SA);
    unsigned sb_base = (unsigned)__cvta_generic_to_shared(SB);

    // stage A: 128 rows x 128 halves = 2048 uint4, 8 per thread
#pragma unroll
    for (int l = 0; l < 8; l++) {
        int idx = tid + l * 256;
        int r = idx >> 4, c8 = (idx & 15) * 8;
        uint4 v = make_uint4(0, 0, 0, 0);
        if (row0 + r < NN)
            v = *(const uint4*)(g_lnh + (size_t)(row0 + r) * 128 + c8);
        *(uint4*)(SA + r * ASTR + c8) = v;
    }
    // stage B k-major from fp16 W: 128 k rows x 128 n halves = 2048 uint4, 8 per thread
#pragma unroll
    for (int l = 0; l < 8; l++) {
        int idx = tid + l * 256;
        int kk = idx >> 4, c8 = (idx & 15) * 8;
        uint4 v = *(const uint4*)(Wh + (size_t)kk * 512 + col0 + c8);
        *(uint4*)(SB + kk * SBSTR + c8) = v;
    }
    __syncthreads();

#pragma unroll
    for (int ks = 0; ks < 128; ks += 16) {
        unsigned af[2][4], bf[4][4];
        int acol = ks + ((lane >= 16) ? 8 : 0);
#pragma unroll
        for (int mf = 0; mf < 2; mf++) {
            int arow = wm * 32 + mf * 16 + (lane & 15);
            ldsm_x4(af[mf], sa_base + (arow * ASTR + acol) * 2);
        }
        int brow = ks + (lane & 15);
#pragma unroll
        for (int nb = 0; nb < 4; nb++) {
            int bcol = wn * 64 + nb * 16 + ((lane >= 16) ? 8 : 0);
            ldsm_x4_trans(bf[nb], sb_base + (brow * SBSTR + bcol) * 2);
        }
#pragma unroll
        for (int mf = 0; mf < 2; mf++) {
#pragma unroll
            for (int nb = 0; nb < 4; nb++) {
                mma16816(acc[mf][nb * 2 + 0], af[mf], &bf[nb][0]);
                mma16816(acc[mf][nb * 2 + 1], af[mf], &bf[nb][2]);
            }
        }
    }

    // epilogue: store xh fp16
#pragma unroll
    for (int mf = 0; mf < 2; mf++) {
#pragma unroll
        for (int nf = 0; nf < 8; nf++) {
            int col = col0 + wn * 64 + nf * 8 + tq * 2;
            int r1 = row0 + wm * 32 + mf * 16 + g;
            int r2 = r1 + 8;
            if (r1 < NN)
                *(__half2*)(g_xh + (size_t)r1 * 512 + col) =
                    __floats2half2_rn(acc[mf][nf][0], acc[mf][nf][1]);
            if (r2 < NN)
                *(__half2*)(g_xh + (size_t)r2 * 512 + col) =
                    __floats2half2_rn(acc[mf][nf][2], acc[mf][nf][3]);
        }
    }
}

// ---------------- aggregation: staged weights + all-lanes gather ----------------
#define CHUNK 128
__device__ __forceinline__ float lrelu(float x) { return x > 0.f ? x : NEG_SLOPE * x; }

__global__ void k_agg(const float* __restrict__ bconv) {
    int n = blockIdx.x;
    int t = threadIdx.x;                  // 128
    int h = t >> 5, lane = t & 31;
    int beg = g_rowptr[n], end = g_rowptr[n + 1];

    __shared__ int   s_src[CHUNK];
    __shared__ float s_w[CHUNK][4];
    __shared__ float s_part[4][HID];

    float4 adv = *(const float4*)(g_ad + (size_t)n * 4);
    const __half* xbase = g_xh + h * 128 + lane * 4;

    float z = 0.f, a0 = 0.f, a1 = 0.f, a2 = 0.f, a3 = 0.f;

    for (int cb = beg; cb < end; cb += CHUNK) {
        int ce = min(end, cb + CHUNK);
        int k = cb + t;
        if (k < ce) {
            int s = g_src[k];
            float4 a = *(const float4*)(g_as + (size_t)s * 4);
            s_src[t] = s;
            s_w[t][0] = __expf(lrelu(a.x + adv.x));
            s_w[t][1] = __expf(lrelu(a.y + adv.y));
            s_w[t][2] = __expf(lrelu(a.z + adv.z));
            s_w[t][3] = __expf(lrelu(a.w + adv.w));
        }
        __syncthreads();
        int cnt = ce - cb;
#pragma unroll 4
        for (int j = 0; j < cnt; j++) {
            float w = s_w[j][h];
            int s = s_src[j];
            uint2 u = *(const uint2*)(xbase + (size_t)s * 512);
            float2 f0 = __half22float2(*(__half2*)&u.x);
            float2 f1 = __half22float2(*(__half2*)&u.y);
            z += w;
            a0 += w * f0.x; a1 += w * f0.y;
            a2 += w * f1.x; a3 += w * f1.y;
        }
        __syncthreads();
    }

    float iz = 1.0f / z;
    *(float4*)(&s_part[h][lane * 4]) = make_float4(a0 * iz, a1 * iz, a2 * iz, a3 * iz);
    __syncthreads();
    float r = 0.25f * (s_part[0][t] + s_part[1][t] + s_part[2][t] + s_part[3][t]) + bconv[t];
    g_h[(size_t)n * HID + t] += fmaxf(r, 0.f);
}

// ---------------- output projection: 2 nodes per block ----------------
__global__ void k_out_proj(const float* __restrict__ W, const float* __restrict__ b,
                           float* __restrict__ out) {
    int half = threadIdx.x >> 6;          // 0 or 1
    int n = blockIdx.x * 2 + half;
    int t = threadIdx.x & 63;
    __shared__ float sh[2][128];
    if (n < NN) {
        sh[half][t] = g_h[(size_t)n * 128 + t];
        sh[half][t + 64] = g_h[(size_t)n * 128 + 64 + t];
    }
    __syncthreads();
    if (n >= NN) return;
    float s = b[t];
#pragma unroll
    for (int k = 0; k < 128; k++) s += sh[half][k] * W[k * 64 + t];
    out[(size_t)n * 64 + t] = s;
}

// ---------------- launch ----------------
extern "C" void kernel_launch(void* const* d_in, const int* in_sizes, int n_in,
                              void* d_out, int out_size) {
    const float* x       = (const float*)d_in[0];
    const int*   ei      = (const int*)d_in[1];
    const float* W_in    = (const float*)d_in[2];
    const float* b_in    = (const float*)d_in[3];
    const float* W_conv  = (const float*)d_in[4];
    const float* att_src = (const float*)d_in[5];
    const float* att_dst = (const float*)d_in[6];
    const float* b_conv  = (const float*)d_in[7];
    const float* ln_g    = (const float*)d_in[8];
    const float* ln_b    = (const float*)d_in[9];
    const float* W_out   = (const float*)d_in[10];
    const float* b_out   = (const float*)d_in[11];
    float* out = (float*)d_out;

    int nblk = (NN + 1023) / 1024;
    k_zero_cnt<<<(NN + 255) / 256, 256>>>();
    k_count<<<(E2 + 255) / 256, 256>>>(ei);
    k_scan1<<<nblk, 1024>>>();
    k_scan2<<<1, 64>>>(nblk);
    k_scan3<<<nblk, 1024>>>();
    k_fill<<<(E2 + 255) / 256, 256>>>(ei);

    k_wcvt<<<(DEPTH * HID * 512 / 4 + 255) / 256, 256>>>(W_conv);
    k_wa<<<DEPTH, 512>>>(W_conv, att_src, att_dst);

    k_in_proj<<<(NN * HID + 255) / 256, 256>>>(x, W_in, b_in);

    dim3 gemmGrid(512 / 128, (NN + 127) / 128);
    for (int i = 0; i < DEPTH; i++) {
        k_lnattn<<<(NN + 3) / 4, 128>>>(i, ln_g + i * HID, ln_b + i * HID);
        k_gemm<<<gemmGrid, 256>>>(i);
        k_agg<<<NN, 128>>>(b_conv + i * HID);
    }

    k_out_proj<<<(NN + 1) / 2, 128>>>(W_out, b_out, out);
}